// round 11
// baseline (speedup 1.0000x reference)
#include <cuda_runtime.h>
#include <math.h>

#define HH 512
#define WW 512
#define PLANE (512*512)
#define SHAPE_OFF (1*PLANE)
#define SIZE_OFF  (1025*PLANE)
#define HEAT_OFF  (1027*PLANE)
#define NPTS 10
#define MM 128
#define CSZ 8                    // cluster size = CTAs per heatmap
#define ROWS_PER_CTA (MM / CSZ)  // 16

__device__ __forceinline__ unsigned int fkey(float v) {
    unsigned int b = __float_as_uint(v);
    return (b & 0x80000000u) ? ~b : (b | 0x80000000u);
}
__device__ __forceinline__ unsigned long long umax64(unsigned long long a,
                                                     unsigned long long b) {
    return a > b ? a : b;
}

// 80 CTAs (8-CTA cluster per heatmap) x 256 threads. Single kernel:
// phase 1: each CTA scans 128KB of its heatmap -> packed partial,
//          pushed to slot[rank] of ALL peers (st.shared::cluster).
// cluster.sync
// phase 2: local 8-slot reduce -> meta -> 16 output rows per CTA.
__global__ void __launch_bounds__(256)
__cluster_dims__(CSZ, 1, 1)
fused_kernel(const float* __restrict__ feat, float* __restrict__ out) {
    __shared__ unsigned long long s_slots[CSZ];
    __shared__ float s_rows[ROWS_PER_CTA][32];  // y-interped rows
    __shared__ int4 s_meta;

    int hm = blockIdx.x >> 3;
    unsigned int rank;
    asm("mov.u32 %0, %%cluster_ctarank;" : "=r"(rank));
    int tid = threadIdx.x;

    const float* heat = feat + HEAT_OFF + (size_t)hm * PLANE;
    int base = (int)rank * 32768;

    // ---- phase 1: scan 32768 floats (32 x float4 per thread) ----
    float bestv = -__int_as_float(0x7F800000);  // -inf
    int   bestq = base;
    float4 bq = make_float4(bestv, bestv, bestv, bestv);
#pragma unroll
    for (int j = 0; j < 32; j++) {
        int e = base + ((j * 256 + tid) << 2);
        float4 v = *reinterpret_cast<const float4*>(heat + e);
        float m = fmaxf(fmaxf(v.x, v.y), fmaxf(v.z, v.w));
        if (m > bestv) { bestv = m; bestq = e; bq = v; }  // strict >: first quad wins
    }
    int off4 = (bq.x == bestv) ? 0 : (bq.y == bestv) ? 1 : (bq.z == bestv) ? 2 : 3;
    unsigned long long best =
        ((unsigned long long)fkey(bestv) << 32) |
        (unsigned int)(~(unsigned int)(bestq + off4));

#pragma unroll
    for (int off = 16; off > 0; off >>= 1)
        best = umax64(best, __shfl_xor_sync(0xFFFFFFFFu, best, off));

    __shared__ unsigned long long s_w[8];
    if ((tid & 31) == 0) s_w[tid >> 5] = best;
    __syncthreads();
    if (tid < 32) {
        unsigned long long v = (tid < 8) ? s_w[tid] : 0ULL;
#pragma unroll
        for (int off = 4; off > 0; off >>= 1)
            v = umax64(v, __shfl_xor_sync(0xFFFFFFFFu, v, off));
        if (tid == 0) {
            // push my partial into slot[rank] of every cluster CTA
            unsigned int laddr;
            asm("{ .reg .u64 t; cvta.to.shared.u64 t, %1; cvt.u32.u64 %0, t; }"
                : "=r"(laddr) : "l"(&s_slots[rank]));
#pragma unroll
            for (int r = 0; r < CSZ; r++) {
                unsigned int raddr;
                asm("mapa.shared::cluster.u32 %0, %1, %2;"
                    : "=r"(raddr) : "r"(laddr), "r"(r));
                asm volatile("st.shared::cluster.u64 [%0], %1;"
                             :: "r"(raddr), "l"(v) : "memory");
            }
        }
    }

    // all partial pushes complete + visible after this
    asm volatile("barrier.cluster.arrive.aligned;" ::: "memory");
    asm volatile("barrier.cluster.wait.aligned;" ::: "memory");

    // ---- phase 2: local reduce of 8 slots -> meta ----
    if (tid < 32) {
        unsigned long long v = (tid < CSZ) ? s_slots[tid] : 0ULL;
#pragma unroll
        for (int off = 4; off > 0; off >>= 1)
            v = umax64(v, __shfl_xor_sync(0xFFFFFFFFu, v, off));
        if (tid == 0) {
            int idx = (int)(~(unsigned int)(v & 0xFFFFFFFFu));
            float hv = fabsf(feat[SIZE_OFF + idx]);
            float wv = fabsf(feat[SIZE_OFF + PLANE + idx]);
            int h = min(max((int)hv, 1), MM);
            int w = min(max((int)wv, 1), MM);
            s_meta = make_int4(idx, h, w, 0);
        }
    }
    __syncthreads();

    int pbase = s_meta.x;
    int h = s_meta.y, w = s_meta.z;
    int py = pbase >> 9;
    int px = pbase & 511;
    float hf = (float)h, wf = (float)w;
    int r0 = (int)rank * ROWS_PER_CTA;

    // saliency loads first (depend only on meta): 8 per thread, independent
    float sal[8];
    bool vmask[8];
#pragma unroll
    for (int k = 0; k < 8; k++) {
        int i = k * 256 + tid;          // 0..2047
        int r = r0 + (i >> 7);
        int c = i & 127;
        int gr = py - (h >> 1) + r;
        int gc = px - (w >> 1) + c;
        bool valid = (r < h) && (c < w) &&
                     (gr >= 0) && (gr < HH) && (gc >= 0) && (gc < WW);
        vmask[k] = valid;
        sal[k] = valid ? feat[gr * WW + gc] : 0.0f;
    }

    // shape gathers + y-interp: 16 rows x 32 cols = 512 entries, 2/thread
#pragma unroll
    for (int k = 0; k < 2; k++) {
        int i = k * 256 + tid;          // 0..511
        int rl = i >> 5;
        int x  = i & 31;
        float sy = ((float)(r0 + rl) + 0.5f) * 32.0f / hf - 0.5f;
        sy = fminf(fmaxf(sy, 0.0f), 31.0f);
        int y0 = (int)floorf(sy);
        int y1 = min(y0 + 1, 31);
        float wy = sy - (float)y0;
        float v0 = feat[SHAPE_OFF + (size_t)(y0 * 32 + x) * PLANE + pbase];
        float v1 = feat[SHAPE_OFF + (size_t)(y1 * 32 + x) * PLANE + pbase];
        s_rows[rl][x] = v0 * (1.0f - wy) + v1 * wy;
    }
    __syncthreads();

    float* o = out + (size_t)hm * (MM * MM) + (size_t)r0 * MM;
#pragma unroll
    for (int k = 0; k < 8; k++) {
        int i = k * 256 + tid;
        int rl = i >> 7;
        int c  = i & 127;
        float sx = ((float)c + 0.5f) * 32.0f / wf - 0.5f;
        sx = fminf(fmaxf(sx, 0.0f), 31.0f);
        int x0 = (int)floorf(sx);
        int x1 = min(x0 + 1, 31);
        float wx = sx - (float)x0;
        float v = s_rows[rl][x0] * (1.0f - wx) + s_rows[rl][x1] * wx;
        float lv = 1.0f / (1.0f + __expf(-v));
        o[i] = vmask[k] ? lv * sal[k] : 0.0f;
    }
}

extern "C" void kernel_launch(void* const* d_in, const int* in_sizes, int n_in,
                              void* d_out, int out_size) {
    const float* feat = (const float*)d_in[0];
    float* out = (float*)d_out;

    cudaLaunchConfig_t cfg = {};
    cfg.gridDim  = dim3(NPTS * CSZ);
    cfg.blockDim = dim3(256);
    cfg.dynamicSmemBytes = 0;
    cudaLaunchAttribute attr[1];
    attr[0].id = cudaLaunchAttributeClusterDimension;
    attr[0].val.clusterDim = {CSZ, 1, 1};
    cfg.attrs = attr;
    cfg.numAttrs = 1;
    cudaLaunchKernelEx(&cfg, fused_kernel, feat, out);
}